// round 3
// baseline (speedup 1.0000x reference)
#include <cuda_runtime.h>

#define BB 2
#define SS 2048
#define HID 1024
#define HEADS 16
#define DH 64
#define INNER 1024

// Scratch (device globals — no allocation allowed)
__device__ float g_q[BB*HEADS*SS*DH];    // [b][h][s][d]
__device__ float g_k[BB*HEADS*SS*DH];
__device__ float g_v[BB*HEADS*SS*DH];
__device__ float g_ctx[BB*SS*INNER];     // [b][s][h*64+d]

// ---------------------------------------------------------------------------
// QKV projection: out[b][h][s][d] = (X @ W + bias)
// grid: (INNER/64, B*S/64, 3), block 256
// ---------------------------------------------------------------------------
__global__ void qkv_proj_kernel(
    const float* __restrict__ Xq, const float* __restrict__ Xk, const float* __restrict__ Xv,
    const float* __restrict__ Wq, const float* __restrict__ Wk, const float* __restrict__ Wv,
    const float* __restrict__ bq, const float* __restrict__ bk, const float* __restrict__ bv)
{
    const float* X; const float* W; const float* bias; float* out;
    int z = blockIdx.z;
    if (z == 0)      { X = Xq; W = Wq; bias = bq; out = g_q; }
    else if (z == 1) { X = Xk; W = Wk; bias = bk; out = g_k; }
    else             { X = Xv; W = Wv; bias = bv; out = g_v; }

    __shared__ float As[64][16];
    __shared__ float Bs[16][64];

    const int tid = threadIdx.x;
    const int tx = tid & 15, ty = tid >> 4;
    const int m0 = blockIdx.y * 64;
    const int n0 = blockIdx.x * 64;

    float acc[4][4] = {};

    for (int k0 = 0; k0 < HID; k0 += 16) {
        {
            int r = tid >> 2, c = (tid & 3) * 4;
            float4 v = *(const float4*)(X + (size_t)(m0 + r) * HID + k0 + c);
            As[r][c] = v.x; As[r][c+1] = v.y; As[r][c+2] = v.z; As[r][c+3] = v.w;
        }
        {
            int r = tid >> 4, c = (tid & 15) * 4;
            float4 v = *(const float4*)(W + (size_t)(k0 + r) * INNER + n0 + c);
            *(float4*)&Bs[r][c] = v;
        }
        __syncthreads();
#pragma unroll
        for (int kk = 0; kk < 16; kk++) {
            float a[4];
#pragma unroll
            for (int i = 0; i < 4; i++) a[i] = As[ty*4 + i][kk];
            float4 b4 = *(float4*)&Bs[kk][tx*4];
            float bb[4] = {b4.x, b4.y, b4.z, b4.w};
#pragma unroll
            for (int i = 0; i < 4; i++)
#pragma unroll
                for (int j = 0; j < 4; j++)
                    acc[i][j] += a[i] * bb[j];
        }
        __syncthreads();
    }

    // store to [b][h][s][d]; n0 is head-aligned (64 == DH)
    const int h = n0 >> 6;
    float4 bias4 = *(const float4*)(bias + n0 + tx*4);
    float bbv[4] = {bias4.x, bias4.y, bias4.z, bias4.w};
#pragma unroll
    for (int i = 0; i < 4; i++) {
        int row = m0 + ty*4 + i;
        int b_idx = row >> 11;          // /2048
        int s_idx = row & 2047;
        float4 r4 = make_float4(acc[i][0] + bbv[0], acc[i][1] + bbv[1],
                                acc[i][2] + bbv[2], acc[i][3] + bbv[3]);
        *(float4*)(out + ((size_t)(b_idx*HEADS + h)*SS + s_idx)*DH + tx*4) = r4;
    }
}

// ---------------------------------------------------------------------------
// Flash attention: scores = (QK^T + bias)/8 + mask, streaming softmax, @V
// grid: (S/64, HEADS, B), block 256, dynamic smem 50176 B
// ---------------------------------------------------------------------------
__global__ void attn_kernel(const float* __restrict__ pb, const float* __restrict__ mask)
{
    extern __shared__ float sm[];
    float* sq = sm;                 // Q tile  [64][64]
    float* kp = sm + 64*64;         // K^T tile [64][68], later P tile [64][64]
    float* sv = kp + 64*68;         // V tile  [64][64]

    const int tid = threadIdx.x;
    const int tx = tid & 15, ty = tid >> 4;
    const int qb = blockIdx.x * 64;
    const int h  = blockIdx.y;
    const int b  = blockIdx.z;

    const float* qptr = g_q + (size_t)(b*HEADS + h)*SS*DH;
    const float* kptr = g_k + (size_t)(b*HEADS + h)*SS*DH;
    const float* vptr = g_v + (size_t)(b*HEADS + h)*SS*DH;

#pragma unroll
    for (int i = 0; i < 16; i++) {
        int idx = i*256 + tid;
        int r = idx >> 6, d = idx & 63;
        sq[r*64 + d] = qptr[(size_t)(qb + r)*DH + d];
    }

    float m_i[4], l_i[4], o[4][4];
#pragma unroll
    for (int i = 0; i < 4; i++) {
        m_i[i] = -1e30f; l_i[i] = 0.f;
#pragma unroll
        for (int j = 0; j < 4; j++) o[i][j] = 0.f;
    }

    for (int kt = 0; kt < SS/64; kt++) {
        const int kb = kt * 64;
        __syncthreads();   // previous P/V reads complete before overwrite
        // load K (transposed in smem) and V
#pragma unroll
        for (int i = 0; i < 16; i++) {
            int idx = i*256 + tid;
            int r = idx >> 6, d = idx & 63;
            float kv = kptr[(size_t)(kb + r)*DH + d];
            kp[d*68 + r] = kv;
            sv[r*64 + d] = vptr[(size_t)(kb + r)*DH + d];
        }
        __syncthreads();

        // S = Q K^T
        float s[4][4] = {};
#pragma unroll
        for (int d = 0; d < 64; d++) {
            float a[4];
#pragma unroll
            for (int i = 0; i < 4; i++) a[i] = sq[(ty*4 + i)*64 + d];
            float4 k4 = *(float4*)&kp[d*68 + tx*4];
            float kk[4] = {k4.x, k4.y, k4.z, k4.w};
#pragma unroll
            for (int i = 0; i < 4; i++)
#pragma unroll
                for (int j = 0; j < 4; j++)
                    s[i][j] += a[i] * kk[j];
        }

        // s = (s + bias)/8 + mask
#pragma unroll
        for (int i = 0; i < 4; i++) {
            int q = qb + ty*4 + i;
            float4 bb = *(const float4*)(pb   + ((size_t)h*SS + q)*SS + kb + tx*4);
            float4 mm = *(const float4*)(mask + ((size_t)b*SS + q)*SS + kb + tx*4);
            s[i][0] = (s[i][0] + bb.x)*0.125f + mm.x;
            s[i][1] = (s[i][1] + bb.y)*0.125f + mm.y;
            s[i][2] = (s[i][2] + bb.z)*0.125f + mm.z;
            s[i][3] = (s[i][3] + bb.w)*0.125f + mm.w;
        }

        // online softmax (rows reduced across the 16 tx lanes)
#pragma unroll
        for (int i = 0; i < 4; i++) {
            float mx = fmaxf(fmaxf(s[i][0], s[i][1]), fmaxf(s[i][2], s[i][3]));
#pragma unroll
            for (int off = 8; off > 0; off >>= 1)
                mx = fmaxf(mx, __shfl_xor_sync(0xffffffffu, mx, off, 16));
            float mn = fmaxf(m_i[i], mx);
            float corr = __expf(m_i[i] - mn);
            m_i[i] = mn;
            float rs = 0.f;
#pragma unroll
            for (int j = 0; j < 4; j++) { s[i][j] = __expf(s[i][j] - mn); rs += s[i][j]; }
#pragma unroll
            for (int off = 8; off > 0; off >>= 1)
                rs += __shfl_xor_sync(0xffffffffu, rs, off, 16);
            l_i[i] = l_i[i]*corr + rs;
#pragma unroll
            for (int j = 0; j < 4; j++) o[i][j] *= corr;
        }

        __syncthreads();   // everyone done reading kp as K^T
        // stash P into kp as [64][64]
#pragma unroll
        for (int i = 0; i < 4; i++) {
            float4 p4 = make_float4(s[i][0], s[i][1], s[i][2], s[i][3]);
            *(float4*)&kp[(ty*4 + i)*64 + tx*4] = p4;
        }
        __syncthreads();

        // O += P @ V
#pragma unroll
        for (int k = 0; k < 64; k++) {
            float p[4];
#pragma unroll
            for (int i = 0; i < 4; i++) p[i] = kp[(ty*4 + i)*64 + k];
            float4 v4 = *(float4*)&sv[k*64 + tx*4];
            float vv[4] = {v4.x, v4.y, v4.z, v4.w};
#pragma unroll
            for (int i = 0; i < 4; i++)
#pragma unroll
                for (int j = 0; j < 4; j++)
                    o[i][j] += p[i] * vv[j];
        }
    }

    // finalize: O / l, store to ctx [b][s][h*64+d]
#pragma unroll
    for (int i = 0; i < 4; i++) {
        float inv = 1.0f / l_i[i];
        int q = qb + ty*4 + i;
        float4 r4 = make_float4(o[i][0]*inv, o[i][1]*inv, o[i][2]*inv, o[i][3]*inv);
        *(float4*)(g_ctx + ((size_t)b*SS + q)*INNER + h*DH + tx*4) = r4;
    }
}

// ---------------------------------------------------------------------------
// Output projection: out = ctx @ Wo + bo
// grid: (HID/64, B*S/64), block 256
// ---------------------------------------------------------------------------
__global__ void out_proj_kernel(const float* __restrict__ Wo, const float* __restrict__ bo,
                                float* __restrict__ out)
{
    __shared__ float As[64][16];
    __shared__ float Bs[16][64];

    const int tid = threadIdx.x;
    const int tx = tid & 15, ty = tid >> 4;
    const int m0 = blockIdx.y * 64;
    const int n0 = blockIdx.x * 64;
    const float* X = g_ctx;

    float acc[4][4] = {};

    for (int k0 = 0; k0 < INNER; k0 += 16) {
        {
            int r = tid >> 2, c = (tid & 3) * 4;
            float4 v = *(const float4*)(X + (size_t)(m0 + r) * INNER + k0 + c);
            As[r][c] = v.x; As[r][c+1] = v.y; As[r][c+2] = v.z; As[r][c+3] = v.w;
        }
        {
            int r = tid >> 4, c = (tid & 15) * 4;
            float4 v = *(const float4*)(Wo + (size_t)(k0 + r) * HID + n0 + c);
            *(float4*)&Bs[r][c] = v;
        }
        __syncthreads();
#pragma unroll
        for (int kk = 0; kk < 16; kk++) {
            float a[4];
#pragma unroll
            for (int i = 0; i < 4; i++) a[i] = As[ty*4 + i][kk];
            float4 b4 = *(float4*)&Bs[kk][tx*4];
            float bb[4] = {b4.x, b4.y, b4.z, b4.w};
#pragma unroll
            for (int i = 0; i < 4; i++)
#pragma unroll
                for (int j = 0; j < 4; j++)
                    acc[i][j] += a[i] * bb[j];
        }
        __syncthreads();
    }

    float4 bias4 = *(const float4*)(bo + n0 + tx*4);
#pragma unroll
    for (int i = 0; i < 4; i++) {
        int row = m0 + ty*4 + i;
        float4 r4 = make_float4(acc[i][0] + bias4.x, acc[i][1] + bias4.y,
                                acc[i][2] + bias4.z, acc[i][3] + bias4.w);
        *(float4*)(out + (size_t)row*HID + n0 + tx*4) = r4;
    }
}

// ---------------------------------------------------------------------------
extern "C" void kernel_launch(void* const* d_in, const int* in_sizes, int n_in,
                              void* d_out, int out_size)
{
    const float* query = (const float*)d_in[0];
    const float* key   = (const float*)d_in[1];
    const float* value = (const float*)d_in[2];
    const float* mask  = (const float*)d_in[3];
    const float* pbias = (const float*)d_in[4];
    const float* Wq = (const float*)d_in[5];
    const float* bq = (const float*)d_in[6];
    const float* Wk = (const float*)d_in[7];
    const float* bk = (const float*)d_in[8];
    const float* Wv = (const float*)d_in[9];
    const float* bv = (const float*)d_in[10];
    const float* Wo = (const float*)d_in[11];
    const float* bo = (const float*)d_in[12];
    float* out = (float*)d_out;

    const int ATTN_SMEM = (64*64 + 64*68 + 64*64) * 4;   // 50176 B
    cudaFuncSetAttribute(attn_kernel, cudaFuncAttributeMaxDynamicSharedMemorySize, ATTN_SMEM);

    dim3 gProj(INNER/64, (BB*SS)/64, 3);
    qkv_proj_kernel<<<gProj, 256>>>(query, key, value, Wq, Wk, Wv, bq, bk, bv);

    dim3 gAttn(SS/64, HEADS, BB);
    attn_kernel<<<gAttn, 256, ATTN_SMEM>>>(pbias, mask);

    dim3 gOut(HID/64, (BB*SS)/64);
    out_proj_kernel<<<gOut, 256>>>(Wo, bo, out);
}

// round 4
// speedup vs baseline: 2.5246x; 2.5246x over previous
#include <cuda_runtime.h>
#include <cstdint>

#define BB 2
#define SS 2048
#define HID 1024
#define HEADS 16
#define DH 64
#define INNER 1024

// Scratch (device globals — no allocation allowed)
__device__ float g_q[BB*HEADS*SS*DH];    // [b][h][s][d]
__device__ float g_k[BB*HEADS*SS*DH];
__device__ float g_v[BB*HEADS*SS*DH];
__device__ float g_ctx[BB*SS*INNER];     // [b][s][h*64+d]

// ---------------------------------------------------------------------------
// tf32 helpers
// ---------------------------------------------------------------------------
__device__ __forceinline__ unsigned f2tf(float x) {
    unsigned r;
    asm("cvt.rna.tf32.f32 %0, %1;" : "=r"(r) : "f"(x));
    return r;
}

__device__ __forceinline__ void mma_tf32(float* d, const unsigned* a,
                                         unsigned b0, unsigned b1, const float* c) {
    asm volatile(
        "mma.sync.aligned.m16n8k8.row.col.f32.tf32.tf32.f32 "
        "{%0,%1,%2,%3}, {%4,%5,%6,%7}, {%8,%9}, {%10,%11,%12,%13};\n"
        : "=f"(d[0]), "=f"(d[1]), "=f"(d[2]), "=f"(d[3])
        : "r"(a[0]), "r"(a[1]), "r"(a[2]), "r"(a[3]),
          "r"(b0), "r"(b1),
          "f"(c[0]), "f"(c[1]), "f"(c[2]), "f"(c[3]));
}

// ---------------------------------------------------------------------------
// GEMM: C[M=4096][N=1024] = X[4096][1024] @ W[1024][1024] + bias
// MODE 1: qkv (z picks X/W/bias; scatter out to [b][h][s][d] device globals)
// MODE 0: out projection (plain row-major out)
// Block: 128 threads (4 warps, 2x2), tile 128x128x16, double buffered.
// ---------------------------------------------------------------------------
#define GK 1024
#define GN 1024
#define LDA 20
#define LDB 136

template<int MODE>
__global__ __launch_bounds__(128)
void gemm_tf32_kernel(const float* __restrict__ X0, const float* __restrict__ X1,
                      const float* __restrict__ X2,
                      const float* __restrict__ W0, const float* __restrict__ W1,
                      const float* __restrict__ W2,
                      const float* __restrict__ bi0, const float* __restrict__ bi1,
                      const float* __restrict__ bi2,
                      float* __restrict__ out0)
{
    __shared__ unsigned As[2][128*LDA];
    __shared__ unsigned Bs[2][16*LDB];

    const float* X; const float* W; const float* bias; float* out;
    if (MODE == 1) {
        int z = blockIdx.z;
        if (z == 0)      { X = X0; W = W0; bias = bi0; out = g_q; }
        else if (z == 1) { X = X1; W = W1; bias = bi1; out = g_k; }
        else             { X = X2; W = W2; bias = bi2; out = g_v; }
    } else {
        X = X0; W = W0; bias = bi0; out = out0;
    }

    const int tid = threadIdx.x;
    const int lane = tid & 31;
    const int warp = tid >> 5;
    const int g = lane >> 2;      // group 0..7
    const int t = lane & 3;       // thread-in-group 0..3
    const int wm = warp >> 1;     // warp m index 0..1
    const int wn = warp & 1;      // warp n index 0..1

    const int m0 = blockIdx.y * 128;
    const int n0 = blockIdx.x * 128;

    // tile-load mappings
    const int rowA = tid >> 2;            // + p*32
    const int cA   = (tid & 3) * 4;
    const int rowB = tid >> 5;            // + p*4
    const int cB   = (tid & 31) * 4;

    float4 ra[4], rb[4];

    auto ldg_tile = [&](int kt) {
        const int k0 = kt * 16;
#pragma unroll
        for (int p = 0; p < 4; p++)
            ra[p] = *(const float4*)(X + (size_t)(m0 + rowA + p*32) * GK + k0 + cA);
#pragma unroll
        for (int p = 0; p < 4; p++)
            rb[p] = *(const float4*)(W + (size_t)(k0 + rowB + p*4) * GN + n0 + cB);
    };
    auto sts_tile = [&](int buf) {
#pragma unroll
        for (int p = 0; p < 4; p++) {
            uint4 u = make_uint4(f2tf(ra[p].x), f2tf(ra[p].y), f2tf(ra[p].z), f2tf(ra[p].w));
            *(uint4*)&As[buf][(rowA + p*32)*LDA + cA] = u;
        }
#pragma unroll
        for (int p = 0; p < 4; p++) {
            uint4 u = make_uint4(f2tf(rb[p].x), f2tf(rb[p].y), f2tf(rb[p].z), f2tf(rb[p].w));
            *(uint4*)&Bs[buf][(rowB + p*4)*LDB + cB] = u;
        }
    };

    float c[4][8][4];
#pragma unroll
    for (int mf = 0; mf < 4; mf++)
#pragma unroll
        for (int nf = 0; nf < 8; nf++)
#pragma unroll
            for (int i = 0; i < 4; i++) c[mf][nf][i] = 0.f;

    ldg_tile(0);
    sts_tile(0);
    __syncthreads();

    for (int kt = 0; kt < GK/16; kt++) {
        const int buf = kt & 1;
        if (kt < GK/16 - 1) ldg_tile(kt + 1);

        const unsigned* A_ = As[buf];
        const unsigned* B_ = Bs[buf];
#pragma unroll
        for (int ks = 0; ks < 2; ks++) {
            unsigned a[4][4];
#pragma unroll
            for (int mf = 0; mf < 4; mf++) {
                int base = (wm*64 + mf*16 + g)*LDA + ks*8 + t;
                a[mf][0] = A_[base];
                a[mf][1] = A_[base + 8*LDA];
                a[mf][2] = A_[base + 4];
                a[mf][3] = A_[base + 8*LDA + 4];
            }
            unsigned bf[8][2];
#pragma unroll
            for (int nf = 0; nf < 8; nf++) {
                int base = (ks*8 + t)*LDB + wn*64 + nf*8 + g;
                bf[nf][0] = B_[base];
                bf[nf][1] = B_[base + 4*LDB];
            }
#pragma unroll
            for (int mf = 0; mf < 4; mf++)
#pragma unroll
                for (int nf = 0; nf < 8; nf++)
                    mma_tf32(c[mf][nf], a[mf], bf[nf][0], bf[nf][1], c[mf][nf]);
        }

        if (kt < GK/16 - 1) {
            sts_tile((kt + 1) & 1);
            __syncthreads();
        }
    }

    // epilogue
#pragma unroll
    for (int mf = 0; mf < 4; mf++) {
        int r0 = m0 + wm*64 + mf*16 + g;
        int r1 = r0 + 8;
#pragma unroll
        for (int nf = 0; nf < 8; nf++) {
            int col = n0 + wn*64 + nf*8 + 2*t;
            float2 bs = *(const float2*)(bias + col);
            float2 v0 = make_float2(c[mf][nf][0] + bs.x, c[mf][nf][1] + bs.y);
            float2 v1 = make_float2(c[mf][nf][2] + bs.x, c[mf][nf][3] + bs.y);
            if (MODE == 1) {
                int h = col >> 6, d = col & 63;
                int b0i = r0 >> 11, s0 = r0 & 2047;
                int b1i = r1 >> 11, s1 = r1 & 2047;
                *(float2*)(out + ((size_t)(b0i*HEADS + h)*SS + s0)*DH + d) = v0;
                *(float2*)(out + ((size_t)(b1i*HEADS + h)*SS + s1)*DH + d) = v1;
            } else {
                *(float2*)(out + (size_t)r0*GN + col) = v0;
                *(float2*)(out + (size_t)r1*GN + col) = v1;
            }
        }
    }
}

// ---------------------------------------------------------------------------
// Flash attention with tf32 mma.
// Block: 128 threads (4 warps), 64 q-rows per block (16 per warp).
// grid: (S/64, HEADS, B). Dynamic smem: Ksm[64][68] + Vsm[64][72] + Psm[64][68]
// ---------------------------------------------------------------------------
#define LDK 68
#define LDV 72
#define LDP 68

__global__ __launch_bounds__(128)
void attn_tf32_kernel(const float* __restrict__ pb, const float* __restrict__ mask)
{
    extern __shared__ unsigned smx[];
    unsigned* Kw = smx;                    // 64*68
    unsigned* Vw = Kw + 64*LDK;            // 64*72
    unsigned* Pw = Vw + 64*LDV;            // 64*68

    const int tid = threadIdx.x;
    const int lane = tid & 31;
    const int w = tid >> 5;
    const int g = lane >> 2;
    const int t = lane & 3;

    const int qb = blockIdx.x * 64;
    const int h  = blockIdx.y;
    const int b  = blockIdx.z;

    const float* qptr = g_q + (size_t)(b*HEADS + h)*SS*DH;
    const float* kptr = g_k + (size_t)(b*HEADS + h)*SS*DH;
    const float* vptr = g_v + (size_t)(b*HEADS + h)*SS*DH;

    // ---- load Q tile into Kw buffer, then Q fragments into registers ----
    {
#pragma unroll
        for (int i = 0; i < 8; i++) {
            int idx4 = i*128 + tid;
            int r = idx4 >> 4, c4 = (idx4 & 15) * 4;
            float4 v = *(const float4*)(qptr + (size_t)(qb + r)*DH + c4);
            uint4 u = make_uint4(f2tf(v.x), f2tf(v.y), f2tf(v.z), f2tf(v.w));
            *(uint4*)&Kw[r*LDK + c4] = u;
        }
    }
    __syncthreads();

    unsigned qa[8][4];
#pragma unroll
    for (int ks = 0; ks < 8; ks++) {
        int base = (w*16 + g)*LDK + ks*8 + t;
        qa[ks][0] = Kw[base];
        qa[ks][1] = Kw[base + 8*LDK];
        qa[ks][2] = Kw[base + 4];
        qa[ks][3] = Kw[base + 8*LDK + 4];
    }

    float o[8][4];
#pragma unroll
    for (int nf = 0; nf < 8; nf++)
#pragma unroll
        for (int i = 0; i < 4; i++) o[nf][i] = 0.f;
    float m0v = -1e30f, m1v = -1e30f, l0 = 0.f, l1 = 0.f;

    const int q0 = qb + w*16 + g;
    const int q1 = q0 + 8;

    for (int kt = 0; kt < SS/64; kt++) {
        const int kb = kt * 64;
        __syncthreads();   // prior K/V reads complete
        // load K and V tiles (tf32 in smem)
#pragma unroll
        for (int i = 0; i < 8; i++) {
            int idx4 = i*128 + tid;
            int r = idx4 >> 4, c4 = (idx4 & 15) * 4;
            float4 kv = *(const float4*)(kptr + (size_t)(kb + r)*DH + c4);
            uint4 ku = make_uint4(f2tf(kv.x), f2tf(kv.y), f2tf(kv.z), f2tf(kv.w));
            *(uint4*)&Kw[r*LDK + c4] = ku;
            float4 vv = *(const float4*)(vptr + (size_t)(kb + r)*DH + c4);
            uint4 vu = make_uint4(f2tf(vv.x), f2tf(vv.y), f2tf(vv.z), f2tf(vv.w));
            *(uint4*)&Vw[r*LDV + c4] = vu;
        }
        __syncthreads();

        // ---- S = Q K^T ----
        float s[8][4];
#pragma unroll
        for (int nf = 0; nf < 8; nf++)
#pragma unroll
            for (int i = 0; i < 4; i++) s[nf][i] = 0.f;

#pragma unroll
        for (int ks = 0; ks < 8; ks++) {
#pragma unroll
            for (int nf = 0; nf < 8; nf++) {
                int base = (nf*8 + g)*LDK + ks*8 + t;
                unsigned b0 = Kw[base];
                unsigned b1 = Kw[base + 4];
                mma_tf32(s[nf], qa[ks], b0, b1, s[nf]);
            }
        }

        // ---- (S + bias)/8 + mask ----
#pragma unroll
        for (int nf = 0; nf < 8; nf++) {
            int col = kb + nf*8 + 2*t;
            float2 pb0 = *(const float2*)(pb + ((size_t)h*SS + q0)*SS + col);
            float2 pb1 = *(const float2*)(pb + ((size_t)h*SS + q1)*SS + col);
            float2 mm0 = *(const float2*)(mask + ((size_t)b*SS + q0)*SS + col);
            float2 mm1 = *(const float2*)(mask + ((size_t)b*SS + q1)*SS + col);
            s[nf][0] = (s[nf][0] + pb0.x)*0.125f + mm0.x;
            s[nf][1] = (s[nf][1] + pb0.y)*0.125f + mm0.y;
            s[nf][2] = (s[nf][2] + pb1.x)*0.125f + mm1.x;
            s[nf][3] = (s[nf][3] + pb1.y)*0.125f + mm1.y;
        }

        // ---- online softmax (row groups of 4 lanes) ----
        float mx0 = -1e30f, mx1 = -1e30f;
#pragma unroll
        for (int nf = 0; nf < 8; nf++) {
            mx0 = fmaxf(mx0, fmaxf(s[nf][0], s[nf][1]));
            mx1 = fmaxf(mx1, fmaxf(s[nf][2], s[nf][3]));
        }
        mx0 = fmaxf(mx0, __shfl_xor_sync(0xffffffffu, mx0, 1));
        mx0 = fmaxf(mx0, __shfl_xor_sync(0xffffffffu, mx0, 2));
        mx1 = fmaxf(mx1, __shfl_xor_sync(0xffffffffu, mx1, 1));
        mx1 = fmaxf(mx1, __shfl_xor_sync(0xffffffffu, mx1, 2));

        float nm0 = fmaxf(m0v, mx0), nm1 = fmaxf(m1v, mx1);
        float corr0 = __expf(m0v - nm0), corr1 = __expf(m1v - nm1);
        m0v = nm0; m1v = nm1;

        float rs0 = 0.f, rs1 = 0.f;
#pragma unroll
        for (int nf = 0; nf < 8; nf++) {
            s[nf][0] = __expf(s[nf][0] - nm0);
            s[nf][1] = __expf(s[nf][1] - nm0);
            s[nf][2] = __expf(s[nf][2] - nm1);
            s[nf][3] = __expf(s[nf][3] - nm1);
            rs0 += s[nf][0] + s[nf][1];
            rs1 += s[nf][2] + s[nf][3];
        }
        rs0 += __shfl_xor_sync(0xffffffffu, rs0, 1);
        rs0 += __shfl_xor_sync(0xffffffffu, rs0, 2);
        rs1 += __shfl_xor_sync(0xffffffffu, rs1, 1);
        rs1 += __shfl_xor_sync(0xffffffffu, rs1, 2);
        l0 = l0*corr0 + rs0;
        l1 = l1*corr1 + rs1;
#pragma unroll
        for (int nf = 0; nf < 8; nf++) {
            o[nf][0] *= corr0; o[nf][1] *= corr0;
            o[nf][2] *= corr1; o[nf][3] *= corr1;
        }

        // ---- P -> smem (per-warp region), reload as A fragments ----
        {
            int pr = w*16 + g;
#pragma unroll
            for (int nf = 0; nf < 8; nf++) {
                int a0 = pr*LDP + nf*8 + 2*t;
                *(uint2*)&Pw[a0]          = make_uint2(f2tf(s[nf][0]), f2tf(s[nf][1]));
                *(uint2*)&Pw[a0 + 8*LDP]  = make_uint2(f2tf(s[nf][2]), f2tf(s[nf][3]));
            }
        }
        __syncwarp();

        // ---- O += P @ V ----
#pragma unroll
        for (int ks = 0; ks < 8; ks++) {
            unsigned pa[4];
            int base = (w*16 + g)*LDP + ks*8 + t;
            pa[0] = Pw[base];
            pa[1] = Pw[base + 8*LDP];
            pa[2] = Pw[base + 4];
            pa[3] = Pw[base + 8*LDP + 4];
#pragma unroll
            for (int nf = 0; nf < 8; nf++) {
                int vb = (ks*8 + t)*LDV + nf*8 + g;
                unsigned b0 = Vw[vb];
                unsigned b1 = Vw[vb + 4*LDV];
                mma_tf32(o[nf], pa, b0, b1, o[nf]);
            }
        }
    }

    // ---- finalize ----
    float inv0 = 1.0f / l0, inv1 = 1.0f / l1;
#pragma unroll
    for (int nf = 0; nf < 8; nf++) {
        int d = nf*8 + 2*t;
        *(float2*)(g_ctx + ((size_t)b*SS + q0)*INNER + h*DH + d)
            = make_float2(o[nf][0]*inv0, o[nf][1]*inv0);
        *(float2*)(g_ctx + ((size_t)b*SS + q1)*INNER + h*DH + d)
            = make_float2(o[nf][2]*inv1, o[nf][3]*inv1);
    }
}

// ---------------------------------------------------------------------------
extern "C" void kernel_launch(void* const* d_in, const int* in_sizes, int n_in,
                              void* d_out, int out_size)
{
    const float* query = (const float*)d_in[0];
    const float* key   = (const float*)d_in[1];
    const float* value = (const float*)d_in[2];
    const float* mask  = (const float*)d_in[3];
    const float* pbias = (const float*)d_in[4];
    const float* Wq = (const float*)d_in[5];
    const float* bq = (const float*)d_in[6];
    const float* Wk = (const float*)d_in[7];
    const float* bk = (const float*)d_in[8];
    const float* Wv = (const float*)d_in[9];
    const float* bv = (const float*)d_in[10];
    const float* Wo = (const float*)d_in[11];
    const float* bo = (const float*)d_in[12];
    float* out = (float*)d_out;

    float* ctx_ptr = nullptr;
    cudaGetSymbolAddress((void**)&ctx_ptr, g_ctx);

    const int ATTN_SMEM = (64*LDK + 64*LDV + 64*LDP) * 4;   // 53248 B
    static bool attr_set = false;
    if (!attr_set) {
        cudaFuncSetAttribute(attn_tf32_kernel,
                             cudaFuncAttributeMaxDynamicSharedMemorySize, ATTN_SMEM);
        attr_set = true;
    }

    // QKV projections
    dim3 gQKV(GN/128, (BB*SS)/128, 3);
    gemm_tf32_kernel<1><<<gQKV, 128>>>(query, key, value, Wq, Wk, Wv,
                                       bq, bk, bv, nullptr);

    // attention
    dim3 gAttn(SS/64, HEADS, BB);
    attn_tf32_kernel<<<gAttn, 128, ATTN_SMEM>>>(pbias, mask);

    // output projection
    dim3 gOut(GN/128, (BB*SS)/128, 1);
    gemm_tf32_kernel<0><<<gOut, 128>>>(ctx_ptr, nullptr, nullptr, Wo, nullptr, nullptr,
                                       bo, nullptr, nullptr, out);
}